// round 8
// baseline (speedup 1.0000x reference)
#include <cuda_runtime.h>

// MaxPool2d k=2 s=2 valid, (32,64,224,224) fp32 -> (32,64,112,112).
// R7 = R3 body (measured per-thread optimum: 8 front-batched independent
// LDG.128 over a 4-row x 8-col input patch, 2 STG.128) with L2 cache-policy
// operands (createpolicy + L2::cache_hint — the form ptxas accepts for
// 128-bit accesses on sm_103):
//   - input:  evict_first (411 MB pure stream, never reused)
//   - output: evict_last  (103 MB output fits ~126 MB L2; graph replays
//     overwrite dirty lines in L2, eliding DRAM write-backs)
// All accesses 16B-aligned.

#define NC_TOTAL   2048              // 32 * 64
#define IH         224
#define IW         224
#define OH         112
#define OW         112
#define IN_PLANE   (IH * IW)         // 50176
#define OUT_PLANE  (OH * OW)         // 12544
#define GROUPS_W   (OW / 4)          // 28 float4 groups per output row
#define ROWPAIRS   (OH / 2)          // 56 output-row pairs
#define TOTAL_THREADS (NC_TOTAL * ROWPAIRS * GROUPS_W)   // 3,211,264

__device__ __forceinline__ float4 ldg_pol(const float4* p, unsigned long long pol) {
    float4 v;
    asm volatile("ld.global.nc.L2::cache_hint.v4.f32 {%0,%1,%2,%3}, [%4], %5;"
                 : "=f"(v.x), "=f"(v.y), "=f"(v.z), "=f"(v.w)
                 : "l"(p), "l"(pol));
    return v;
}

__device__ __forceinline__ void stg_pol(float4* p, float4 v, unsigned long long pol) {
    asm volatile("st.global.L2::cache_hint.v4.f32 [%0], {%1,%2,%3,%4}, %5;"
                 :: "l"(p), "f"(v.x), "f"(v.y), "f"(v.z), "f"(v.w), "l"(pol)
                 : "memory");
}

__device__ __forceinline__ float4 pool2(const float4 a0, const float4 a1,
                                        const float4 b0, const float4 b1) {
    float4 o;
    o.x = fmaxf(fmaxf(a0.x, a0.y), fmaxf(b0.x, b0.y));
    o.y = fmaxf(fmaxf(a0.z, a0.w), fmaxf(b0.z, b0.w));
    o.z = fmaxf(fmaxf(a1.x, a1.y), fmaxf(b1.x, b1.y));
    o.w = fmaxf(fmaxf(a1.z, a1.w), fmaxf(b1.z, b1.w));
    return o;
}

__global__ __launch_bounds__(256)
void maxpool2d_k2s2_l2pin_kernel(const float* __restrict__ in, float* __restrict__ out) {
    int idx = blockIdx.x * blockDim.x + threadIdx.x;
    if (idx >= TOTAL_THREADS) return;

    // Per-thread cache policies (uniform -> hoisted to UR by ptxas).
    unsigned long long pol_ld, pol_st;
    asm volatile("createpolicy.fractional.L2::evict_first.b64 %0, 1.0;" : "=l"(pol_ld));
    asm volatile("createpolicy.fractional.L2::evict_last.b64 %0, 1.0;"  : "=l"(pol_st));

    int w8  = idx % GROUPS_W;            // output col group (4 cols -> 8 input cols)
    int t   = idx / GROUPS_W;
    int ohp = t % ROWPAIRS;              // which pair of output rows
    int nc  = t / ROWPAIRS;

    const int rstep = IW / 4;            // 56 float4 per input row
    const float4* r0 = reinterpret_cast<const float4*>(
        in + (size_t)nc * IN_PLANE + (size_t)(ohp * 4) * IW) + w8 * 2;

    // Front-batch all 8 independent 128-bit loads (single batch, no mid-thread
    // consumption point — the structure that measured fastest).
    float4 a0 = ldg_pol(r0 + 0 * rstep + 0, pol_ld);
    float4 a1 = ldg_pol(r0 + 0 * rstep + 1, pol_ld);
    float4 b0 = ldg_pol(r0 + 1 * rstep + 0, pol_ld);
    float4 b1 = ldg_pol(r0 + 1 * rstep + 1, pol_ld);
    float4 c0 = ldg_pol(r0 + 2 * rstep + 0, pol_ld);
    float4 c1 = ldg_pol(r0 + 2 * rstep + 1, pol_ld);
    float4 d0 = ldg_pol(r0 + 3 * rstep + 0, pol_ld);
    float4 d1 = ldg_pol(r0 + 3 * rstep + 1, pol_ld);

    float4* orow0 = reinterpret_cast<float4*>(
        out + (size_t)nc * OUT_PLANE + (size_t)(ohp * 2) * OW) + w8;
    float4* orow1 = orow0 + (OW / 4);

    stg_pol(orow0, pool2(a0, a1, b0, b1), pol_st);
    stg_pol(orow1, pool2(c0, c1, d0, d1), pol_st);
}

extern "C" void kernel_launch(void* const* d_in, const int* in_sizes, int n_in,
                              void* d_out, int out_size) {
    const float* in = (const float*)d_in[0];
    float* out = (float*)d_out;
    int blocks = (TOTAL_THREADS + 255) / 256;   // 12544
    maxpool2d_k2s2_l2pin_kernel<<<blocks, 256>>>(in, out);
}

// round 9
// speedup vs baseline: 1.0510x; 1.0510x over previous
#include <cuda_runtime.h>

// MaxPool2d k=2 s=2 valid, (32,64,224,224) fp32 -> (32,64,112,112).
// R8: persistent grid-stride version of the R3 body (measured per-thread
// optimum: 8 front-batched independent LDG.128 over a 4-row x 8-col input
// patch, 2 STG.128). Grid = 148 SMs x 8 resident CTAs = 1184 CTAs; each
// thread loops ~10-11 iterations. Eliminates ~10 wave transitions + tail,
// and pipelines loads across loop iterations. Plain cache policy (best
// timed variant; streaming/evict hints measured neutral-to-harmful).
// All accesses 16B-aligned.

#define NC_TOTAL   2048              // 32 * 64
#define IH         224
#define IW         224
#define OH         112
#define OW         112
#define IN_PLANE   (IH * IW)         // 50176
#define OUT_PLANE  (OH * OW)         // 12544
#define GROUPS_W   (OW / 4)          // 28 float4 groups per output row
#define ROWPAIRS   (OH / 2)          // 56 output-row pairs
#define TOTAL_WORK (NC_TOTAL * ROWPAIRS * GROUPS_W)   // 3,211,264 work items
#define NBLOCKS    1184              // 148 SMs * 8 CTAs
#define NTHREADS   256

__device__ __forceinline__ float4 pool2(const float4 a0, const float4 a1,
                                        const float4 b0, const float4 b1) {
    float4 o;
    o.x = fmaxf(fmaxf(a0.x, a0.y), fmaxf(b0.x, b0.y));
    o.y = fmaxf(fmaxf(a0.z, a0.w), fmaxf(b0.z, b0.w));
    o.z = fmaxf(fmaxf(a1.x, a1.y), fmaxf(b1.x, b1.y));
    o.w = fmaxf(fmaxf(a1.z, a1.w), fmaxf(b1.z, b1.w));
    return o;
}

__global__ __launch_bounds__(NTHREADS)
void maxpool2d_k2s2_pers_kernel(const float* __restrict__ in, float* __restrict__ out) {
    const int stride = NBLOCKS * NTHREADS;   // 303,104 threads

    for (int idx = blockIdx.x * NTHREADS + threadIdx.x; idx < TOTAL_WORK; idx += stride) {
        int w8  = idx % GROUPS_W;            // output col group (4 cols -> 8 input cols)
        int t   = idx / GROUPS_W;
        int ohp = t % ROWPAIRS;              // which pair of output rows
        int nc  = t / ROWPAIRS;

        const int rstep = IW / 4;            // 56 float4 per input row
        const float4* r0 = reinterpret_cast<const float4*>(
            in + (size_t)nc * IN_PLANE + (size_t)(ohp * 4) * IW) + w8 * 2;

        // Front-batch all 8 independent 128-bit loads.
        float4 a0 = r0[0 * rstep + 0];
        float4 a1 = r0[0 * rstep + 1];
        float4 b0 = r0[1 * rstep + 0];
        float4 b1 = r0[1 * rstep + 1];
        float4 c0 = r0[2 * rstep + 0];
        float4 c1 = r0[2 * rstep + 1];
        float4 d0 = r0[3 * rstep + 0];
        float4 d1 = r0[3 * rstep + 1];

        float4* orow0 = reinterpret_cast<float4*>(
            out + (size_t)nc * OUT_PLANE + (size_t)(ohp * 2) * OW) + w8;
        float4* orow1 = orow0 + (OW / 4);

        orow0[0] = pool2(a0, a1, b0, b1);
        orow1[0] = pool2(c0, c1, d0, d1);
    }
}

extern "C" void kernel_launch(void* const* d_in, const int* in_sizes, int n_in,
                              void* d_out, int out_size) {
    const float* in = (const float*)d_in[0];
    float* out = (float*)d_out;
    maxpool2d_k2s2_pers_kernel<<<NBLOCKS, NTHREADS>>>(in, out);
}

// round 10
// speedup vs baseline: 1.1135x; 1.0595x over previous
#include <cuda_runtime.h>

// MaxPool2d k=2 s=2 valid, (32,64,224,224) fp32 -> (32,64,112,112).
// R9 = the untested best-of-both cell: R3's measured-optimal body
// (8 front-batched independent LDG.128 over a 4-row x 8-col input patch,
// 2 STG.128, one thread = 2x4 output patch, one-shot grid) with PLAIN
// cache operators (streaming/evict hints measured neutral-to-harmful in
// the timed replay steady state; plain ops measured best on the clock).
// Pure HBM stream: 411 MB read + 103 MB write, zero reuse. All 16B-aligned.

#define NC_TOTAL   2048              // 32 * 64
#define IH         224
#define IW         224
#define OH         112
#define OW         112
#define IN_PLANE   (IH * IW)         // 50176
#define OUT_PLANE  (OH * OW)         // 12544
#define GROUPS_W   (OW / 4)          // 28 float4 groups per output row
#define ROWPAIRS   (OH / 2)          // 56 output-row pairs
#define TOTAL_THREADS (NC_TOTAL * ROWPAIRS * GROUPS_W)   // 3,211,264

__device__ __forceinline__ float4 pool2(const float4 a0, const float4 a1,
                                        const float4 b0, const float4 b1) {
    float4 o;
    o.x = fmaxf(fmaxf(a0.x, a0.y), fmaxf(b0.x, b0.y));
    o.y = fmaxf(fmaxf(a0.z, a0.w), fmaxf(b0.z, b0.w));
    o.z = fmaxf(fmaxf(a1.x, a1.y), fmaxf(b1.x, b1.y));
    o.w = fmaxf(fmaxf(a1.z, a1.w), fmaxf(b1.z, b1.w));
    return o;
}

__global__ __launch_bounds__(256)
void maxpool2d_k2s2_x2p_kernel(const float* __restrict__ in, float* __restrict__ out) {
    int idx = blockIdx.x * blockDim.x + threadIdx.x;
    if (idx >= TOTAL_THREADS) return;

    int w8  = idx % GROUPS_W;            // output col group (4 cols -> 8 input cols)
    int t   = idx / GROUPS_W;
    int ohp = t % ROWPAIRS;              // which pair of output rows
    int nc  = t / ROWPAIRS;

    const int rstep = IW / 4;            // 56 float4 per input row
    const float4* r0 = reinterpret_cast<const float4*>(
        in + (size_t)nc * IN_PLANE + (size_t)(ohp * 4) * IW) + w8 * 2;

    // Front-batch all 8 independent 128-bit loads (single batch, no
    // mid-thread consumption point).
    float4 a0 = r0[0 * rstep + 0];
    float4 a1 = r0[0 * rstep + 1];
    float4 b0 = r0[1 * rstep + 0];
    float4 b1 = r0[1 * rstep + 1];
    float4 c0 = r0[2 * rstep + 0];
    float4 c1 = r0[2 * rstep + 1];
    float4 d0 = r0[3 * rstep + 0];
    float4 d1 = r0[3 * rstep + 1];

    float4* orow0 = reinterpret_cast<float4*>(
        out + (size_t)nc * OUT_PLANE + (size_t)(ohp * 2) * OW) + w8;
    float4* orow1 = orow0 + (OW / 4);

    orow0[0] = pool2(a0, a1, b0, b1);
    orow1[0] = pool2(c0, c1, d0, d1);
}

extern "C" void kernel_launch(void* const* d_in, const int* in_sizes, int n_in,
                              void* d_out, int out_size) {
    const float* in = (const float*)d_in[0];
    float* out = (float*)d_out;
    int blocks = (TOTAL_THREADS + 255) / 256;   // 12544
    maxpool2d_k2s2_x2p_kernel<<<blocks, 256>>>(in, out);
}